// round 11
// baseline (speedup 1.0000x reference)
#include <cuda_runtime.h>
#include <cstdint>
#include <math.h>

#define N 8192
#define D 512
#define BM 128
#define NT (N / BM)                 // 64
#define NPAIRS (NT * (NT + 1) / 2)  // 2080
#define UNITS (NPAIRS * 2)          // 4160 half-tiles: 128 rows x 64 cols
#define BKC 128                     // fp8 K per chunk (128B rows)
#define NCHUNKS (D / BKC)           // 4
#define TILE_A 16384                // 128 rows x 128B
#define TILE_B 8192                 //  64 rows x 128B
#define STAGE_BYTES (TILE_A + TILE_B)          // 24576
#define SMEM_BYTES (1024 + 3 * STAGE_BYTES)    // 74752 -> 3 CTAs/SM

__device__ uint8_t g_q[N * D];
__device__ float   g_scale[N];
__device__ double  g_accum;

// ---------------------------------------------------------------------------
// PTX helpers (arch-agnostic)
// ---------------------------------------------------------------------------
__device__ __forceinline__ uint32_t smem_u32(const void* p) {
    uint32_t a;
    asm("{ .reg .u64 t; cvta.to.shared.u64 t, %1; cvt.u32.u64 %0, t; }" : "=r"(a) : "l"(p));
    return a;
}
__device__ __forceinline__ void cp16(uint32_t saddr, const void* g) {
    asm volatile("cp.async.cg.shared.global [%0], [%1], 16;" :: "r"(saddr), "l"(g) : "memory");
}
__device__ __forceinline__ void cp_commit() {
    asm volatile("cp.async.commit_group;" ::: "memory");
}
template <int NN>
__device__ __forceinline__ void cp_wait() {
    asm volatile("cp.async.wait_group %0;" :: "n"(NN) : "memory");
}
__device__ __forceinline__ void ldsm_x4(uint32_t* r, uint32_t addr) {
    asm volatile("ldmatrix.sync.aligned.m8n8.x4.shared.b16 {%0,%1,%2,%3}, [%4];"
                 : "=r"(r[0]), "=r"(r[1]), "=r"(r[2]), "=r"(r[3]) : "r"(addr));
}
__device__ __forceinline__ void qmma16832(float* d, const uint32_t* a,
                                          uint32_t b0, uint32_t b1) {
    asm volatile(
        "mma.sync.aligned.m16n8k32.row.col.f32.e4m3.e4m3.f32 "
        "{%0,%1,%2,%3}, {%4,%5,%6,%7}, {%8,%9}, {%0,%1,%2,%3};"
        : "+f"(d[0]), "+f"(d[1]), "+f"(d[2]), "+f"(d[3])
        : "r"(a[0]), "r"(a[1]), "r"(a[2]), "r"(a[3]), "r"(b0), "r"(b1));
}
__device__ __forceinline__ uint32_t cvt_e4m3x2(float hi, float lo) {
    uint16_t h;
    asm("cvt.rn.satfinite.e4m3x2.f32 %0, %1, %2;" : "=h"(h) : "f"(hi), "f"(lo));
    return (uint32_t)h;
}

// ---------------------------------------------------------------------------
// Kernel 1: row L2-normalize + e4m3 quantize. One WARP per row.
// ---------------------------------------------------------------------------
__global__ __launch_bounds__(256) void quantize_kernel(const float* __restrict__ in) {
    int row  = blockIdx.x * 8 + (threadIdx.x >> 5);
    int lane = threadIdx.x & 31;
    if (blockIdx.x == 0 && threadIdx.x == 0) g_accum = 0.0;

    const float4* src = (const float4*)(in + (size_t)row * D);
    float4 v[4];
    float ss = 0.0f;
    #pragma unroll
    for (int i = 0; i < 4; i++) {
        v[i] = src[i * 32 + lane];
        ss += v[i].x * v[i].x + v[i].y * v[i].y + v[i].z * v[i].z + v[i].w * v[i].w;
    }
    #pragma unroll
    for (int o = 16; o; o >>= 1) ss += __shfl_xor_sync(0xffffffffu, ss, o);
    float inv = rsqrtf(ss);

    float amax = 0.0f;
    #pragma unroll
    for (int i = 0; i < 4; i++)
        amax = fmaxf(amax, fmaxf(fmaxf(fabsf(v[i].x), fabsf(v[i].y)),
                                 fmaxf(fabsf(v[i].z), fabsf(v[i].w))));
    amax *= inv;
    #pragma unroll
    for (int o = 16; o; o >>= 1) amax = fmaxf(amax, __shfl_xor_sync(0xffffffffu, amax, o));

    float s    = amax * (1.0f / 448.0f);
    float qmul = inv * (448.0f / amax);
    if (lane == 0) g_scale[row] = s;

    uint32_t* dq = (uint32_t*)(g_q + (size_t)row * D);
    #pragma unroll
    for (int i = 0; i < 4; i++) {
        uint32_t l16 = cvt_e4m3x2(v[i].y * qmul, v[i].x * qmul);
        uint32_t h16 = cvt_e4m3x2(v[i].w * qmul, v[i].z * qmul);
        dq[i * 32 + lane] = l16 | (h16 << 16);
    }
}

// ---------------------------------------------------------------------------
// Kernel 2: QMMA over 4160 half-tiles (128 rows x 64 cols), 3 CTAs/SM.
// 8 warps: 4 over M (32 rows each) x 2 over N (32 cols each); warp tile 32x32.
// ldsm addresses precomputed: addr(kk) = C ^ (kk<<5) (bases 128B-aligned).
// ---------------------------------------------------------------------------
extern __shared__ char dynsmem[];

__global__ __launch_bounds__(256, 3) void gram_qmma_kernel() {
    int u = blockIdx.x;
    int tile = u >> 1, half = u & 1;
    int bj = (int)((sqrtf(8.0f * (float)tile + 1.0f) - 1.0f) * 0.5f);
    while ((bj + 1) * (bj + 2) / 2 <= tile) bj++;
    while (bj * (bj + 1) / 2 > tile) bj--;
    int bi = tile - bj * (bj + 1) / 2;
    const bool diag = (bi == bj);
    int brow0 = bj * BM + half * 64;

    const uint8_t* __restrict__ gA = g_q + (size_t)bi * BM * D;
    const uint8_t* __restrict__ gB = g_q + (size_t)brow0 * D;

    int t    = threadIdx.x;
    int wid  = t >> 5;
    int lane = t & 31;
    int wm   = wid & 3;    // 4 warps over M
    int wn   = wid >> 2;   // 2 warps over N

    __shared__ float sScale[192];   // [0..127]=A rows, [128..191]=B rows
    if (t < 128)      sScale[t] = g_scale[bi * BM + t];
    else if (t < 192) sScale[t] = g_scale[brow0 + (t - 128)];

    uint32_t smem0 = smem_u32(dynsmem);
    uint32_t base  = (smem0 + 1023) & ~1023u;
    uint32_t sA[3], sB[3];
    #pragma unroll
    for (int s = 0; s < 3; s++) {
        sA[s] = base + s * STAGE_BYTES;
        sB[s] = sA[s] + TILE_A;
    }

    // ---- ldsm address constants: addr(kk) = (stagebase + C) ^ (kk<<5) ----
    // row r for both A and B frags: group_row + (lane&15); r&7 == lane&7.
    int r7   = lane & 7;
    int a_kh = lane >> 4;                        // bit0 of kchunk
    uint32_t swc = (uint32_t)((((r7 >> 1) & 3) << 5) | ((a_kh ^ (r7 & 1)) << 4));
    int arow = wm * 32 + (lane & 15);            // + mi*16
    int brow = wn * 32 + (lane & 15);            // + p*16
    uint32_t cA0 = (uint32_t)(arow * 128)        + swc;
    uint32_t cA1 = (uint32_t)((arow + 16) * 128) + swc;
    uint32_t cB0 = (uint32_t)(brow * 128)        + swc;
    uint32_t cB1 = (uint32_t)((brow + 16) * 128) + swc;

    // ---- async tile loaders ----
    // A: 128 rows x 128B: thread t -> row t>>1, chunks (t&1)*4 + i
    // B:  64 rows x 128B: thread t -> row t>>2, chunks (t&3)*2 + i
    int la_row = t >> 1;
    int lb_row = t >> 2;
    const char* gpA = (const char*)(gA + (size_t)la_row * D);
    const char* gpB = (const char*)(gB + (size_t)lb_row * D);
    uint32_t soffA[4], soffB[2];
    #pragma unroll
    for (int i = 0; i < 4; i++) {
        uint32_t c = (uint32_t)((t & 1) * 4 + i);
        soffA[i] = (uint32_t)la_row * 128 + ((c ^ (la_row & 7)) << 4);
    }
    #pragma unroll
    for (int i = 0; i < 2; i++) {
        uint32_t c = (uint32_t)((t & 3) * 2 + i);
        soffB[i] = (uint32_t)lb_row * 128 + ((c ^ (lb_row & 7)) << 4);
    }
    auto load_stage = [&](int s, int k0) {
        #pragma unroll
        for (int i = 0; i < 4; i++)
            cp16(sA[s] + soffA[i], gpA + k0 + ((t & 1) * 4 + i) * 16);
        #pragma unroll
        for (int i = 0; i < 2; i++)
            cp16(sB[s] + soffB[i], gpB + k0 + ((t & 3) * 2 + i) * 16);
        cp_commit();
    };

    float acc[2][4][4];
    #pragma unroll
    for (int mi = 0; mi < 2; mi++)
        #pragma unroll
        for (int nj = 0; nj < 4; nj++)
            #pragma unroll
            for (int r = 0; r < 4; r++) acc[mi][nj][r] = 0.0f;

    load_stage(0, 0);
    load_stage(1, BKC);

    for (int c = 0; c < NCHUNKS; c++) {
        if (c < NCHUNKS - 1) cp_wait<1>(); else cp_wait<0>();
        __syncthreads();

        if (c + 2 < NCHUNKS) load_stage((c + 2) % 3, (c + 2) * BKC);

        uint32_t aA0 = sA[c % 3] + cA0, aA1 = sA[c % 3] + cA1;
        uint32_t aB0 = sB[c % 3] + cB0, aB1 = sB[c % 3] + cB1;
        #pragma unroll
        for (int kk = 0; kk < 4; kk++) {
            uint32_t x = (uint32_t)(kk << 5);
            uint32_t Af[2][4], Bf[2][4];
            ldsm_x4(Af[0], aA0 ^ x);
            ldsm_x4(Af[1], aA1 ^ x);
            ldsm_x4(Bf[0], aB0 ^ x);
            ldsm_x4(Bf[1], aB1 ^ x);
            #pragma unroll
            for (int mi = 0; mi < 2; mi++)
                #pragma unroll
                for (int nj = 0; nj < 4; nj++)
                    qmma16832(acc[mi][nj], Af[mi],
                              Bf[nj >> 1][nj & 1], Bf[nj >> 1][(nj & 1) + 2]);
        }
    }

    // Epilogue: scale (s_i*s_j), relu, strict-upper mask on diagonal tiles.
    int lrow0 = wm * 32 + (lane >> 2);
    int lcol0 = wn * 32 + (lane & 3) * 2;

    float si[2][2], sj[4][2];
    #pragma unroll
    for (int mi = 0; mi < 2; mi++)
        #pragma unroll
        for (int h = 0; h < 2; h++)
            si[mi][h] = sScale[lrow0 + mi * 16 + h * 8];
    #pragma unroll
    for (int nj = 0; nj < 4; nj++)
        #pragma unroll
        for (int bc = 0; bc < 2; bc++)
            sj[nj][bc] = sScale[128 + lcol0 + nj * 8 + bc];

    float local = 0.0f;
    #pragma unroll
    for (int mi = 0; mi < 2; mi++)
        #pragma unroll
        for (int nj = 0; nj < 4; nj++)
            #pragma unroll
            for (int r = 0; r < 4; r++) {
                int h  = r >> 1, bc = r & 1;
                int im = lrow0 + mi * 16 + h * 8;
                int jl = lcol0 + nj * 8 + bc;          // 0..63 within half
                float d = acc[mi][nj][r];
                bool ok = diag ? (im < half * 64 + jl) : true;
                if (ok && d > 0.0f) local += d * si[mi][h] * sj[nj][bc];
            }

    #pragma unroll
    for (int o = 16; o; o >>= 1) local += __shfl_xor_sync(0xffffffffu, local, o);
    __shared__ float red[8];
    if (lane == 0) red[wid] = local;
    __syncthreads();
    if (t == 0) {
        float s = 0.0f;
        #pragma unroll
        for (int w = 0; w < 8; w++) s += red[w];
        atomicAdd(&g_accum, (double)s);
    }
}

// ---------------------------------------------------------------------------
// Kernel 3: finalize.
// ---------------------------------------------------------------------------
__global__ void finalize_kernel(float* __restrict__ out, int out_size) {
    double v = 2.0 * g_accum / ((double)N * (double)N);
    float f = (float)v;
    out[0] = f;
    if (out_size > 1) out[1] = f;
}

extern "C" void kernel_launch(void* const* d_in, const int* in_sizes, int n_in,
                              void* d_out, int out_size) {
    const float* id = (const float*)d_in[0];
    cudaFuncSetAttribute(gram_qmma_kernel, cudaFuncAttributeMaxDynamicSharedMemorySize,
                         SMEM_BYTES);
    quantize_kernel<<<N / 8, 256>>>(id);
    gram_qmma_kernel<<<UNITS, 256, SMEM_BYTES>>>();
    finalize_kernel<<<1, 1>>>((float*)d_out, out_size);
}

// round 12
// speedup vs baseline: 1.1582x; 1.1582x over previous
#include <cuda_runtime.h>
#include <cuda_fp16.h>
#include <cstdint>
#include <math.h>

#define N 8192
#define D 512
#define BM 128
#define NT (N / BM)                 // 64
#define NPAIRS (NT * (NT + 1) / 2)  // 2080
#define BKC 128                     // fp8 K elements per chunk (128B rows)
#define NCHUNKS (D / BKC)           // 4
#define NSTAGE 3
#define TILE_BYTES (BM * BKC)       // 16384
#define SMEM_BYTES (1024 + 2 * NSTAGE * TILE_BYTES)
#define QMAX 28.0f                  // fp8 target max; keeps f16 dot_q < 65504

__device__ uint8_t g_q[N * D];
__device__ float   g_scale[N];
__device__ double  g_accum;

// ---------------------------------------------------------------------------
// PTX helpers (arch-agnostic)
// ---------------------------------------------------------------------------
__device__ __forceinline__ uint32_t smem_u32(const void* p) {
    uint32_t a;
    asm("{ .reg .u64 t; cvta.to.shared.u64 t, %1; cvt.u32.u64 %0, t; }" : "=r"(a) : "l"(p));
    return a;
}
__device__ __forceinline__ void cp16(uint32_t saddr, const void* g) {
    asm volatile("cp.async.cg.shared.global [%0], [%1], 16;" :: "r"(saddr), "l"(g) : "memory");
}
__device__ __forceinline__ void cp_commit() {
    asm volatile("cp.async.commit_group;" ::: "memory");
}
template <int NN>
__device__ __forceinline__ void cp_wait() {
    asm volatile("cp.async.wait_group %0;" :: "n"(NN) : "memory");
}
__device__ __forceinline__ void ldsm_x4(uint32_t* r, uint32_t addr) {
    asm volatile("ldmatrix.sync.aligned.m8n8.x4.shared.b16 {%0,%1,%2,%3}, [%4];"
                 : "=r"(r[0]), "=r"(r[1]), "=r"(r[2]), "=r"(r[3]) : "r"(addr));
}
// fp8 e4m3, k=32, f16 accumulate (halves acc regs; potential double-rate)
__device__ __forceinline__ void qmma16832_f16(uint32_t* d, const uint32_t* a,
                                              uint32_t b0, uint32_t b1) {
    asm volatile(
        "mma.sync.aligned.m16n8k32.row.col.f16.e4m3.e4m3.f16 "
        "{%0,%1}, {%2,%3,%4,%5}, {%6,%7}, {%0,%1};"
        : "+r"(d[0]), "+r"(d[1])
        : "r"(a[0]), "r"(a[1]), "r"(a[2]), "r"(a[3]), "r"(b0), "r"(b1));
}
__device__ __forceinline__ uint32_t cvt_e4m3x2(float hi, float lo) {
    uint16_t h;
    asm("cvt.rn.satfinite.e4m3x2.f32 %0, %1, %2;" : "=h"(h) : "f"(hi), "f"(lo));
    return (uint32_t)h;
}

// ---------------------------------------------------------------------------
// Kernel 1: row L2-normalize + e4m3 quantize (qmax = 28). One WARP per row.
// ---------------------------------------------------------------------------
__global__ __launch_bounds__(256) void quantize_kernel(const float* __restrict__ in) {
    int row  = blockIdx.x * 8 + (threadIdx.x >> 5);
    int lane = threadIdx.x & 31;
    if (blockIdx.x == 0 && threadIdx.x == 0) g_accum = 0.0;

    const float4* src = (const float4*)(in + (size_t)row * D);
    float4 v[4];
    float ss = 0.0f;
    #pragma unroll
    for (int i = 0; i < 4; i++) {
        v[i] = src[i * 32 + lane];
        ss += v[i].x * v[i].x + v[i].y * v[i].y + v[i].z * v[i].z + v[i].w * v[i].w;
    }
    #pragma unroll
    for (int o = 16; o; o >>= 1) ss += __shfl_xor_sync(0xffffffffu, ss, o);
    float inv = rsqrtf(ss);

    float amax = 0.0f;
    #pragma unroll
    for (int i = 0; i < 4; i++)
        amax = fmaxf(amax, fmaxf(fmaxf(fabsf(v[i].x), fabsf(v[i].y)),
                                 fmaxf(fabsf(v[i].z), fabsf(v[i].w))));
    amax *= inv;
    #pragma unroll
    for (int o = 16; o; o >>= 1) amax = fmaxf(amax, __shfl_xor_sync(0xffffffffu, amax, o));

    float s    = amax * (1.0f / QMAX);
    float qmul = inv * (QMAX / amax);
    if (lane == 0) g_scale[row] = s;

    uint32_t* dq = (uint32_t*)(g_q + (size_t)row * D);
    #pragma unroll
    for (int i = 0; i < 4; i++) {
        uint32_t l16 = cvt_e4m3x2(v[i].y * qmul, v[i].x * qmul);
        uint32_t h16 = cvt_e4m3x2(v[i].w * qmul, v[i].z * qmul);
        dq[i * 32 + lane] = l16 | (h16 << 16);
    }
}

// ---------------------------------------------------------------------------
// Kernel 2: upper-triangle 128x128 Gram tiles, QMMA e4m3 / f16 acc.
// 256 threads = 8 warps (2 M x 4 N), warp tile 64x32; 3-stage cp.async.
// ldsm addresses: (stage + C) ^ (kk<<5); fragments double-buffered.
// ---------------------------------------------------------------------------
extern __shared__ char dynsmem[];

__global__ __launch_bounds__(256, 2) void gram_qmma_kernel() {
    int b = blockIdx.x;
    int bj = (int)((sqrtf(8.0f * (float)b + 1.0f) - 1.0f) * 0.5f);
    while ((bj + 1) * (bj + 2) / 2 <= b) bj++;
    while (bj * (bj + 1) / 2 > b) bj--;
    int bi = b - bj * (bj + 1) / 2;
    const bool diag = (bi == bj);

    const uint8_t* __restrict__ gA = g_q + (size_t)bi * BM * D;
    const uint8_t* __restrict__ gB = g_q + (size_t)bj * BM * D;

    int t      = threadIdx.x;
    int wid    = t >> 5;
    int lane   = t & 31;
    int warp_m = wid & 1;
    int warp_n = wid >> 1;

    __shared__ float sScale[256];
    if (t < 128) sScale[t] = g_scale[bi * BM + t];
    else         sScale[t] = g_scale[bj * BM + (t - 128)];

    uint32_t smem0 = smem_u32(dynsmem);
    uint32_t base  = (smem0 + 1023) & ~1023u;
    uint32_t sA[NSTAGE], sB[NSTAGE];
    #pragma unroll
    for (int s = 0; s < NSTAGE; s++) {
        sA[s] = base + (2 * s)     * TILE_BYTES;
        sB[s] = base + (2 * s + 1) * TILE_BYTES;
    }

    // ---- ldsm constants: addr(kk) = (stage + C) ^ (kk<<5) ----
    int r7   = lane & 7;
    int a_kh = lane >> 4;
    uint32_t swz = (uint32_t)(((a_kh ^ (r7 & 1)) << 4) | (((r7 >> 1) & 3) << 5));
    int arow = warp_m * 64 + (lane & 15);
    int brow = warp_n * 32 + (lane & 7) + (((lane >> 3) & 1) << 3);
    uint32_t cA[4], cB[2];
    #pragma unroll
    for (int mi = 0; mi < 4; mi++) cA[mi] = (uint32_t)((arow + mi * 16) * 128) + swz;
    #pragma unroll
    for (int p = 0; p < 2; p++)   cB[p]  = (uint32_t)((brow + p * 16) * 128) + swz;

    // ---- async tile loader offsets ----
    int la_row = t >> 1;
    const char* gpA = (const char*)(gA + (size_t)la_row * D);
    const char* gpB = (const char*)(gB + (size_t)la_row * D);
    uint32_t soff[4];
    #pragma unroll
    for (int i = 0; i < 4; i++) {
        uint32_t c = (uint32_t)((t & 1) * 4 + i);
        soff[i] = (uint32_t)la_row * 128 + ((c ^ (la_row & 7)) << 4);
    }
    auto load_stage = [&](int s, int k0) {
        #pragma unroll
        for (int i = 0; i < 4; i++) {
            int gofs = k0 + ((t & 1) * 4 + i) * 16;
            cp16(sA[s] + soff[i], gpA + gofs);
            cp16(sB[s] + soff[i], gpB + gofs);
        }
        cp_commit();
    };

    uint32_t acc[4][4][2];
    #pragma unroll
    for (int mi = 0; mi < 4; mi++)
        #pragma unroll
        for (int nj = 0; nj < 4; nj++) { acc[mi][nj][0] = 0u; acc[mi][nj][1] = 0u; }

    load_stage(0, 0);
    load_stage(1, BKC);

    uint32_t Af[2][4][4], Bf[2][2][4];

    for (int c = 0; c < NCHUNKS; c++) {
        if (c < NCHUNKS - 1) cp_wait<1>(); else cp_wait<0>();
        __syncthreads();

        if (c + 2 < NCHUNKS) load_stage((c + 2) % NSTAGE, (c + 2) * BKC);

        uint32_t aBase = sA[c % NSTAGE], bBase = sB[c % NSTAGE];
        uint32_t eA[4], eB[2];
        #pragma unroll
        for (int mi = 0; mi < 4; mi++) eA[mi] = aBase + cA[mi];
        #pragma unroll
        for (int p = 0; p < 2; p++)   eB[p]  = bBase + cB[p];

        // load fragments for kk = 0
        #pragma unroll
        for (int mi = 0; mi < 4; mi++) ldsm_x4(Af[0][mi], eA[mi]);
        #pragma unroll
        for (int p = 0; p < 2; p++)    ldsm_x4(Bf[0][p],  eB[p]);

        #pragma unroll
        for (int kk = 0; kk < 4; kk++) {
            int cur = kk & 1;
            if (kk < 3) {
                uint32_t x = (uint32_t)((kk + 1) << 5);
                #pragma unroll
                for (int mi = 0; mi < 4; mi++) ldsm_x4(Af[cur ^ 1][mi], eA[mi] ^ x);
                #pragma unroll
                for (int p = 0; p < 2; p++)    ldsm_x4(Bf[cur ^ 1][p],  eB[p] ^ x);
            }
            #pragma unroll
            for (int mi = 0; mi < 4; mi++)
                #pragma unroll
                for (int nj = 0; nj < 4; nj++)
                    qmma16832_f16(acc[mi][nj], Af[cur][mi],
                                  Bf[cur][nj >> 1][nj & 1], Bf[cur][nj >> 1][(nj & 1) + 2]);
        }
    }

    // Epilogue: scale (s_i*s_j), relu, strict-upper mask on diagonal tiles.
    // f16 acc layout: reg r: rows lrow0 + r*8, packed col pair (cn, cn+1).
    int lrow0 = warp_m * 64 + (lane >> 2);
    int lcol0 = warp_n * 32 + (lane & 3) * 2;

    float si[4][2], sj[4][2];
    #pragma unroll
    for (int mi = 0; mi < 4; mi++)
        #pragma unroll
        for (int h = 0; h < 2; h++)
            si[mi][h] = sScale[lrow0 + mi * 16 + h * 8];
    #pragma unroll
    for (int nj = 0; nj < 4; nj++)
        #pragma unroll
        for (int bc = 0; bc < 2; bc++)
            sj[nj][bc] = sScale[128 + lcol0 + nj * 8 + bc];

    float local = 0.0f;
    #pragma unroll
    for (int mi = 0; mi < 4; mi++)
        #pragma unroll
        for (int nj = 0; nj < 4; nj++) {
            int rm = lrow0 + mi * 16;
            int cn = lcol0 + nj * 8;
            #pragma unroll
            for (int r = 0; r < 2; r++) {
                int im = rm + r * 8;
                float2 f2 = __half22float2(*(__half2*)&acc[mi][nj][r]);
                float d0 = f2.x * si[mi][r] * sj[nj][0];
                float d1 = f2.y * si[mi][r] * sj[nj][1];
                bool ok0 = diag ? (im < cn) : true;
                bool ok1 = diag ? (im < cn + 1) : true;
                if (ok0 && d0 > 0.0f) local += d0;
                if (ok1 && d1 > 0.0f) local += d1;
            }
        }

    #pragma unroll
    for (int o = 16; o; o >>= 1) local += __shfl_xor_sync(0xffffffffu, local, o);
    __shared__ float red[8];
    if (lane == 0) red[wid] = local;
    __syncthreads();
    if (t == 0) {
        float s = 0.0f;
        #pragma unroll
        for (int w = 0; w < 8; w++) s += red[w];
        atomicAdd(&g_accum, (double)s);
    }
}

// ---------------------------------------------------------------------------
// Kernel 3: finalize.
// ---------------------------------------------------------------------------
__global__ void finalize_kernel(float* __restrict__ out, int out_size) {
    double v = 2.0 * g_accum / ((double)N * (double)N);
    float f = (float)v;
    out[0] = f;
    if (out_size > 1) out[1] = f;
}

extern "C" void kernel_launch(void* const* d_in, const int* in_sizes, int n_in,
                              void* d_out, int out_size) {
    const float* id = (const float*)d_in[0];
    cudaFuncSetAttribute(gram_qmma_kernel, cudaFuncAttributeMaxDynamicSharedMemorySize,
                         SMEM_BYTES);
    quantize_kernel<<<N / 8, 256>>>(id);
    gram_qmma_kernel<<<NPAIRS, 256, SMEM_BYTES>>>();
    finalize_kernel<<<1, 1>>>((float*)d_out, out_size);
}